// round 1
// baseline (speedup 1.0000x reference)
#include <cuda_runtime.h>
#include <cstdint>

#define NR   65536
#define CIN  256
#define COUT 128
#define KOFF 8
#define CNT  (KOFF * NR)         // 524288 rows for BN stats

#define BM 128
#define BN 128
#define BK 32
#define ASTRIDE (BK + 4)         // 36 floats: conflict-free A-frag reads
#define BSTRIDE (BN + 4)         // 132 floats

__device__ __align__(16) float g_sum[COUT];
__device__ __align__(16) float g_sumsq[COUT];
__device__ __align__(16) float g_sa[COUT];
__device__ __align__(16) float g_sb[COUT];

__global__ void k_zero() {
    int t = threadIdx.x;
    if (t < COUT) { g_sum[t] = 0.f; g_sumsq[t] = 0.f; }
}

__device__ __forceinline__ float f2tf32(float x) {
    uint32_t u;
    asm("cvt.rna.tf32.f32 %0, %1;" : "=r"(u) : "f"(x));
    return __uint_as_float(u);
}

__device__ __forceinline__ void mma8(float* c, const uint32_t* a, uint32_t b0, uint32_t b1) {
    asm volatile(
        "mma.sync.aligned.m16n8k8.row.col.f32.tf32.tf32.f32 "
        "{%0,%1,%2,%3}, {%4,%5,%6,%7}, {%8,%9}, {%0,%1,%2,%3};"
        : "+f"(c[0]), "+f"(c[1]), "+f"(c[2]), "+f"(c[3])
        : "r"(a[0]), "r"(a[1]), "r"(a[2]), "r"(a[3]), "r"(b0), "r"(b1));
}

// C[M=65536, N=1024] = X[65536,256] @ B[256,1024], B col block k = W[k] (k = blockIdx.x)
// Writes raw result to out[(k*NR + m)*128 + d] and accumulates per-d sum/sumsq.
__global__ __launch_bounds__(256) void k_gemm(const float* __restrict__ X,
                                              const float* __restrict__ W,
                                              float* __restrict__ out) {
    __shared__ __align__(16) float As[BM][ASTRIDE];
    __shared__ __align__(16) float Bs[BK][BSTRIDE];
    __shared__ float s_sum[COUT];
    __shared__ float s_sq[COUT];

    const int tid = threadIdx.x;
    const int bx = blockIdx.x;      // k offset 0..7
    const int by = blockIdx.y;      // m tile 0..511
    const int m0 = by * BM;
    const int lane = tid & 31, wid = tid >> 5;
    const int wm = wid >> 1, wn = wid & 1;   // 4x2 warp grid, 32x64 per warp

    if (tid < COUT) { s_sum[tid] = 0.f; s_sq[tid] = 0.f; }

    float c[2][8][4];
#pragma unroll
    for (int i = 0; i < 2; i++)
#pragma unroll
        for (int j = 0; j < 8; j++)
#pragma unroll
            for (int l = 0; l < 4; l++) c[i][j][l] = 0.f;

    const float* Wg = W + bx * (CIN * COUT);

    // per-thread global-load coordinates (4 float4 each for A and B tile)
    int ar[4], ac[4], br[4], bc[4];
#pragma unroll
    for (int i = 0; i < 4; i++) {
        int f = tid + i * 256;
        ar[i] = f >> 3;  ac[i] = (f & 7) * 4;    // A: 128 rows x 8 float4
        br[i] = f >> 5;  bc[i] = (f & 31) * 4;   // B: 32 rows x 32 float4
    }

    float4 aR[4], bR[4];
#pragma unroll
    for (int i = 0; i < 4; i++) {
        aR[i] = *(const float4*)&X[(m0 + ar[i]) * CIN + ac[i]];
        bR[i] = *(const float4*)&Wg[br[i] * COUT + bc[i]];
    }

    const int NK = CIN / BK;   // 8
    for (int t = 0; t < NK; t++) {
#pragma unroll
        for (int i = 0; i < 4; i++) {
            float4 v = aR[i];
            v.x = f2tf32(v.x); v.y = f2tf32(v.y); v.z = f2tf32(v.z); v.w = f2tf32(v.w);
            *(float4*)&As[ar[i]][ac[i]] = v;
            float4 w = bR[i];
            w.x = f2tf32(w.x); w.y = f2tf32(w.y); w.z = f2tf32(w.z); w.w = f2tf32(w.w);
            *(float4*)&Bs[br[i]][bc[i]] = w;
        }
        __syncthreads();

        if (t + 1 < NK) {
            int kk = (t + 1) * BK;
#pragma unroll
            for (int i = 0; i < 4; i++) {
                aR[i] = *(const float4*)&X[(m0 + ar[i]) * CIN + kk + ac[i]];
                bR[i] = *(const float4*)&Wg[(kk + br[i]) * COUT + bc[i]];
            }
        }

#pragma unroll
        for (int ks = 0; ks < 4; ks++) {
            const int k8 = ks * 8;
            uint32_t a[2][4];
#pragma unroll
            for (int mt = 0; mt < 2; mt++) {
                int r = wm * 32 + mt * 16 + (lane >> 2);
                a[mt][0] = __float_as_uint(As[r][k8 + (lane & 3)]);
                a[mt][1] = __float_as_uint(As[r + 8][k8 + (lane & 3)]);
                a[mt][2] = __float_as_uint(As[r][k8 + (lane & 3) + 4]);
                a[mt][3] = __float_as_uint(As[r + 8][k8 + (lane & 3) + 4]);
            }
#pragma unroll
            for (int nt = 0; nt < 8; nt++) {
                int nb = wn * 64 + nt * 8 + (lane >> 2);
                uint32_t b0 = __float_as_uint(Bs[k8 + (lane & 3)][nb]);
                uint32_t b1 = __float_as_uint(Bs[k8 + (lane & 3) + 4][nb]);
                mma8(c[0][nt], a[0], b0, b1);
                mma8(c[1][nt], a[1], b0, b1);
            }
        }
        __syncthreads();
    }

    // ---- epilogue: raw write (k = bx) ----
    float* og = out + ((size_t)bx * NR + m0) * COUT;
#pragma unroll
    for (int mt = 0; mt < 2; mt++) {
#pragma unroll
        for (int nt = 0; nt < 8; nt++) {
            int r = wm * 32 + mt * 16 + (lane >> 2);
            int col = wn * 64 + nt * 8 + 2 * (lane & 3);
            *(float2*)&og[(size_t)r * COUT + col] =
                make_float2(c[mt][nt][0], c[mt][nt][1]);
            *(float2*)&og[(size_t)(r + 8) * COUT + col] =
                make_float2(c[mt][nt][2], c[mt][nt][3]);
        }
    }

    // ---- per-channel sum / sumsq: thread -> shfl -> smem -> global ----
#pragma unroll
    for (int nt = 0; nt < 8; nt++) {
        float s0 = 0.f, s1 = 0.f, q0 = 0.f, q1 = 0.f;
#pragma unroll
        for (int mt = 0; mt < 2; mt++) {
            float v0 = c[mt][nt][0], v1 = c[mt][nt][1];
            float v2 = c[mt][nt][2], v3 = c[mt][nt][3];
            s0 += v0 + v2;           s1 += v1 + v3;
            q0 += v0 * v0 + v2 * v2; q1 += v1 * v1 + v3 * v3;
        }
#pragma unroll
        for (int off = 4; off < 32; off <<= 1) {
            s0 += __shfl_xor_sync(0xffffffffu, s0, off);
            s1 += __shfl_xor_sync(0xffffffffu, s1, off);
            q0 += __shfl_xor_sync(0xffffffffu, q0, off);
            q1 += __shfl_xor_sync(0xffffffffu, q1, off);
        }
        if (lane < 4) {
            int col = wn * 64 + nt * 8 + 2 * lane;
            atomicAdd(&s_sum[col],     s0); atomicAdd(&s_sum[col + 1], s1);
            atomicAdd(&s_sq[col],      q0); atomicAdd(&s_sq[col + 1],  q1);
        }
    }
    __syncthreads();
    if (tid < COUT) {
        atomicAdd(&g_sum[tid],   s_sum[tid]);
        atomicAdd(&g_sumsq[tid], s_sq[tid]);
    }
}

__global__ void k_stats(const float* __restrict__ gamma, const float* __restrict__ beta) {
    int t = threadIdx.x;
    if (t < COUT) {
        const float inv = 1.0f / (float)CNT;
        float mean = g_sum[t] * inv;
        float var  = g_sumsq[t] * inv - mean * mean;
        float A = gamma[t] * rsqrtf(var + 1e-5f);
        g_sa[t] = A;
        g_sb[t] = beta[t] - mean * A;
    }
}

__global__ __launch_bounds__(256) void k_bnrelu(float* __restrict__ o) {
    int i = blockIdx.x * 256 + threadIdx.x;          // one float4 per thread
    float4* o4 = (float4*)o;
    const float4* a4 = (const float4*)g_sa;
    const float4* b4 = (const float4*)g_sb;
    float4 v = o4[i];
    float4 a = a4[i & 31], b = b4[i & 31];           // (4i % 128)/4 == i % 32
    v.x = fmaxf(fmaf(v.x, a.x, b.x), 0.f);
    v.y = fmaxf(fmaf(v.y, a.y, b.y), 0.f);
    v.z = fmaxf(fmaf(v.z, a.z, b.z), 0.f);
    v.w = fmaxf(fmaf(v.w, a.w, b.w), 0.f);
    o4[i] = v;
}

extern "C" void kernel_launch(void* const* d_in, const int* in_sizes, int n_in,
                              void* d_out, int out_size) {
    const float* X     = (const float*)d_in[0];   // [65536, 256]
    const float* W     = (const float*)d_in[1];   // [8, 256, 128]
    const float* gamma = (const float*)d_in[2];   // [128]
    const float* beta  = (const float*)d_in[3];   // [128]
    float* out = (float*)d_out;                   // [8*65536, 128] fp32

    k_zero<<<1, 128>>>();
    dim3 grid(KOFF, NR / BM);                     // (8, 512)
    k_gemm<<<grid, 256>>>(X, W, out);
    k_stats<<<1, 128>>>(gamma, beta);
    k_bnrelu<<<(KOFF * NR * COUT) / 4 / 256, 256>>>(out);
}

// round 2
// speedup vs baseline: 1.0007x; 1.0007x over previous
#include <cuda_runtime.h>
#include <cstdint>

#define NR   65536
#define CIN  256
#define COUT 128
#define KOFF 8
#define CNT  (KOFF * NR)         // 524288 rows for BN stats

#define BM 128
#define BN 128
#define BK 32
#define ASTRIDE (BK + 4)         // 36 floats: conflict-free A-frag reads
#define BSTRIDE (BN + 4)         // 132 floats

__device__ __align__(16) float g_sum[COUT];
__device__ __align__(16) float g_sumsq[COUT];
__device__ __align__(16) float g_sa[COUT];
__device__ __align__(16) float g_sb[COUT];

__global__ void k_zero() {
    int t = threadIdx.x;
    if (t < COUT) { g_sum[t] = 0.f; g_sumsq[t] = 0.f; }
}

__device__ __forceinline__ float f2tf32(float x) {
    uint32_t u;
    asm("cvt.rna.tf32.f32 %0, %1;" : "=r"(u) : "f"(x));
    return __uint_as_float(u);
}

__device__ __forceinline__ void mma8(float* c, const uint32_t* a, uint32_t b0, uint32_t b1) {
    asm volatile(
        "mma.sync.aligned.m16n8k8.row.col.f32.tf32.tf32.f32 "
        "{%0,%1,%2,%3}, {%4,%5,%6,%7}, {%8,%9}, {%0,%1,%2,%3};"
        : "+f"(c[0]), "+f"(c[1]), "+f"(c[2]), "+f"(c[3])
        : "r"(a[0]), "r"(a[1]), "r"(a[2]), "r"(a[3]), "r"(b0), "r"(b1));
}

// C[M=65536, N=1024] = X[65536,256] @ B[256,1024], B col block k = W[k] (k = blockIdx.x)
// Writes raw result to out[(k*NR + m)*128 + d] and accumulates per-d sum/sumsq.
__global__ __launch_bounds__(256) void k_gemm(const float* __restrict__ X,
                                              const float* __restrict__ W,
                                              float* __restrict__ out) {
    __shared__ __align__(16) float As[BM][ASTRIDE];
    __shared__ __align__(16) float Bs[BK][BSTRIDE];
    __shared__ float s_sum[COUT];
    __shared__ float s_sq[COUT];

    const int tid = threadIdx.x;
    const int bx = blockIdx.x;      // k offset 0..7
    const int by = blockIdx.y;      // m tile 0..511
    const int m0 = by * BM;
    const int lane = tid & 31, wid = tid >> 5;
    const int wm = wid >> 1, wn = wid & 1;   // 4x2 warp grid, 32x64 per warp

    if (tid < COUT) { s_sum[tid] = 0.f; s_sq[tid] = 0.f; }

    float c[2][8][4];
#pragma unroll
    for (int i = 0; i < 2; i++)
#pragma unroll
        for (int j = 0; j < 8; j++)
#pragma unroll
            for (int l = 0; l < 4; l++) c[i][j][l] = 0.f;

    const float* Wg = W + bx * (CIN * COUT);

    // per-thread global-load coordinates (4 float4 each for A and B tile)
    int ar[4], ac[4], br[4], bc[4];
#pragma unroll
    for (int i = 0; i < 4; i++) {
        int f = tid + i * 256;
        ar[i] = f >> 3;  ac[i] = (f & 7) * 4;    // A: 128 rows x 8 float4
        br[i] = f >> 5;  bc[i] = (f & 31) * 4;   // B: 32 rows x 32 float4
    }

    float4 aR[4], bR[4];
#pragma unroll
    for (int i = 0; i < 4; i++) {
        aR[i] = *(const float4*)&X[(m0 + ar[i]) * CIN + ac[i]];
        bR[i] = *(const float4*)&Wg[br[i] * COUT + bc[i]];
    }

    const int NK = CIN / BK;   // 8
    for (int t = 0; t < NK; t++) {
#pragma unroll
        for (int i = 0; i < 4; i++) {
            float4 v = aR[i];
            v.x = f2tf32(v.x); v.y = f2tf32(v.y); v.z = f2tf32(v.z); v.w = f2tf32(v.w);
            *(float4*)&As[ar[i]][ac[i]] = v;
            float4 w = bR[i];
            w.x = f2tf32(w.x); w.y = f2tf32(w.y); w.z = f2tf32(w.z); w.w = f2tf32(w.w);
            *(float4*)&Bs[br[i]][bc[i]] = w;
        }
        __syncthreads();

        if (t + 1 < NK) {
            int kk = (t + 1) * BK;
#pragma unroll
            for (int i = 0; i < 4; i++) {
                aR[i] = *(const float4*)&X[(m0 + ar[i]) * CIN + kk + ac[i]];
                bR[i] = *(const float4*)&Wg[(kk + br[i]) * COUT + bc[i]];
            }
        }

#pragma unroll
        for (int ks = 0; ks < 4; ks++) {
            const int k8 = ks * 8;
            uint32_t a[2][4];
#pragma unroll
            for (int mt = 0; mt < 2; mt++) {
                int r = wm * 32 + mt * 16 + (lane >> 2);
                a[mt][0] = __float_as_uint(As[r][k8 + (lane & 3)]);
                a[mt][1] = __float_as_uint(As[r + 8][k8 + (lane & 3)]);
                a[mt][2] = __float_as_uint(As[r][k8 + (lane & 3) + 4]);
                a[mt][3] = __float_as_uint(As[r + 8][k8 + (lane & 3) + 4]);
            }
#pragma unroll
            for (int nt = 0; nt < 8; nt++) {
                int nb = wn * 64 + nt * 8 + (lane >> 2);
                uint32_t b0 = __float_as_uint(Bs[k8 + (lane & 3)][nb]);
                uint32_t b1 = __float_as_uint(Bs[k8 + (lane & 3) + 4][nb]);
                mma8(c[0][nt], a[0], b0, b1);
                mma8(c[1][nt], a[1], b0, b1);
            }
        }
        __syncthreads();
    }

    // ---- epilogue: raw write (k = bx) ----
    float* og = out + ((size_t)bx * NR + m0) * COUT;
#pragma unroll
    for (int mt = 0; mt < 2; mt++) {
#pragma unroll
        for (int nt = 0; nt < 8; nt++) {
            int r = wm * 32 + mt * 16 + (lane >> 2);
            int col = wn * 64 + nt * 8 + 2 * (lane & 3);
            *(float2*)&og[(size_t)r * COUT + col] =
                make_float2(c[mt][nt][0], c[mt][nt][1]);
            *(float2*)&og[(size_t)(r + 8) * COUT + col] =
                make_float2(c[mt][nt][2], c[mt][nt][3]);
        }
    }

    // ---- per-channel sum / sumsq: thread -> shfl -> smem -> global ----
#pragma unroll
    for (int nt = 0; nt < 8; nt++) {
        float s0 = 0.f, s1 = 0.f, q0 = 0.f, q1 = 0.f;
#pragma unroll
        for (int mt = 0; mt < 2; mt++) {
            float v0 = c[mt][nt][0], v1 = c[mt][nt][1];
            float v2 = c[mt][nt][2], v3 = c[mt][nt][3];
            s0 += v0 + v2;           s1 += v1 + v3;
            q0 += v0 * v0 + v2 * v2; q1 += v1 * v1 + v3 * v3;
        }
#pragma unroll
        for (int off = 4; off < 32; off <<= 1) {
            s0 += __shfl_xor_sync(0xffffffffu, s0, off);
            s1 += __shfl_xor_sync(0xffffffffu, s1, off);
            q0 += __shfl_xor_sync(0xffffffffu, q0, off);
            q1 += __shfl_xor_sync(0xffffffffu, q1, off);
        }
        if (lane < 4) {
            int col = wn * 64 + nt * 8 + 2 * lane;
            atomicAdd(&s_sum[col],     s0); atomicAdd(&s_sum[col + 1], s1);
            atomicAdd(&s_sq[col],      q0); atomicAdd(&s_sq[col + 1],  q1);
        }
    }
    __syncthreads();
    if (tid < COUT) {
        atomicAdd(&g_sum[tid],   s_sum[tid]);
        atomicAdd(&g_sumsq[tid], s_sq[tid]);
    }
}

__global__ void k_stats(const float* __restrict__ gamma, const float* __restrict__ beta) {
    int t = threadIdx.x;
    if (t < COUT) {
        const float inv = 1.0f / (float)CNT;
        float mean = g_sum[t] * inv;
        float var  = g_sumsq[t] * inv - mean * mean;
        float A = gamma[t] * rsqrtf(var + 1e-5f);
        g_sa[t] = A;
        g_sb[t] = beta[t] - mean * A;
    }
}

__global__ __launch_bounds__(256) void k_bnrelu(float* __restrict__ o) {
    int i = blockIdx.x * 256 + threadIdx.x;          // one float4 per thread
    float4* o4 = (float4*)o;
    const float4* a4 = (const float4*)g_sa;
    const float4* b4 = (const float4*)g_sb;
    float4 v = o4[i];
    float4 a = a4[i & 31], b = b4[i & 31];           // (4i % 128)/4 == i % 32
    v.x = fmaxf(fmaf(v.x, a.x, b.x), 0.f);
    v.y = fmaxf(fmaf(v.y, a.y, b.y), 0.f);
    v.z = fmaxf(fmaf(v.z, a.z, b.z), 0.f);
    v.w = fmaxf(fmaf(v.w, a.w, b.w), 0.f);
    o4[i] = v;
}

extern "C" void kernel_launch(void* const* d_in, const int* in_sizes, int n_in,
                              void* d_out, int out_size) {
    const float* X     = (const float*)d_in[0];   // [65536, 256]
    const float* W     = (const float*)d_in[1];   // [8, 256, 128]
    const float* gamma = (const float*)d_in[2];   // [128]
    const float* beta  = (const float*)d_in[3];   // [128]
    float* out = (float*)d_out;                   // [8*65536, 128] fp32

    k_zero<<<1, 128>>>();
    dim3 grid(KOFF, NR / BM);                     // (8, 512)
    k_gemm<<<grid, 256>>>(X, W, out);
    k_stats<<<1, 128>>>(gamma, beta);
    k_bnrelu<<<(KOFF * NR * COUT) / 4 / 256, 256>>>(out);
}

// round 4
// speedup vs baseline: 1.4365x; 1.4355x over previous
#include <cuda_runtime.h>
#include <cstdint>

#define NR 65536
#define CIN 256
#define COUT 128
#define KOFF 8
#define CNTF 524288.0f

#define BM 128
#define BN 256            // spans 2 k-offsets
#define BK 32
#define AST 36            // padded stride (floats)
#define BST 36
#define STG_A (BM * AST)          // 4608 floats
#define STG_B (BN * BST)          // 9216 floats
#define STAGE (STG_A + STG_B)     // 13824 floats per stage
#define NSTAGE 3
#define SMEM_BYTES ((NSTAGE * STAGE + 256) * 4)   // + stats

__device__ __align__(16) float g_Wt[KOFF * COUT * CIN];   // [n=k*128+d][c], tf32-rna
__device__ __align__(16) float g_sum[COUT];
__device__ __align__(16) float g_sumsq[COUT];
__device__ __align__(16) float g_sa[COUT];
__device__ __align__(16) float g_sb[COUT];

__device__ __forceinline__ float f2tf32(float x) {
    uint32_t u; asm("cvt.rna.tf32.f32 %0, %1;" : "=r"(u) : "f"(x));
    return __uint_as_float(u);
}
__device__ __forceinline__ uint32_t smem_u32(const void* p) {
    uint32_t a;
    asm("{ .reg .u64 t; cvta.to.shared.u64 t, %1; cvt.u32.u64 %0, t; }" : "=r"(a) : "l"(p));
    return a;
}
__device__ __forceinline__ void cpa16(uint32_t s, const float* g) {
    asm volatile("cp.async.cg.shared.global [%0], [%1], 16;" :: "r"(s), "l"(g));
}
#define CP_COMMIT() asm volatile("cp.async.commit_group;" ::: "memory")
#define CP_WAIT1()  asm volatile("cp.async.wait_group 1;" ::: "memory")
#define CP_WAIT0()  asm volatile("cp.async.wait_group 0;" ::: "memory")

__device__ __forceinline__ void mma8(float* c, const uint32_t* a, uint32_t b0, uint32_t b1) {
    asm volatile(
        "mma.sync.aligned.m16n8k8.row.col.f32.tf32.tf32.f32 "
        "{%0,%1,%2,%3}, {%4,%5,%6,%7}, {%8,%9}, {%0,%1,%2,%3};"
        : "+f"(c[0]), "+f"(c[1]), "+f"(c[2]), "+f"(c[3])
        : "r"(a[0]), "r"(a[1]), "r"(a[2]), "r"(a[3]), "r"(b0), "r"(b1));
}

__global__ void k_zero() {
    int t = threadIdx.x;
    if (t < COUT) { g_sum[t] = 0.f; g_sumsq[t] = 0.f; }
}

// g_Wt[n][c] = rna_tf32(W[k][c][d]) with n = k*128 + d
__global__ void k_wt(const float* __restrict__ W) {
    int idx = blockIdx.x * 256 + threadIdx.x;   // 262144
    int n = idx >> 8, c = idx & 255;
    int k = n >> 7, d = n & 127;
    g_Wt[idx] = f2tf32(W[(k << 15) + (c << 7) + d]);
}

__global__ __launch_bounds__(256, 1)
void k_gemm(const float* __restrict__ X, float* __restrict__ out) {
    extern __shared__ float sm[];
    float* ssum = sm + NSTAGE * STAGE;
    float* ssq  = ssum + COUT;

    const int tid = threadIdx.x, lane = tid & 31, wid = tid >> 5;
    const int wm = wid >> 2, wn = wid & 3;       // 2x4 warps, 64x64 tiles
    const int bxp = blockIdx.x;                  // 0..3 (pair of k-offsets)
    const int m0 = blockIdx.y * BM;

    if (tid < COUT) { ssum[tid] = 0.f; ssq[tid] = 0.f; }

    const float* Ag = X + (size_t)m0 * CIN;
    const float* Bg = g_Wt + (size_t)(bxp * BN) * CIN;
    const uint32_t smb = smem_u32(sm);

    // cp.async coordinates
    int gAo[4]; uint32_t sAo[4];
#pragma unroll
    for (int i = 0; i < 4; i++) {
        int f = tid + i * 256, r = f >> 3, c4 = (f & 7) * 4;
        gAo[i] = r * CIN + c4;
        sAo[i] = (uint32_t)(r * AST + c4) * 4;
    }
    int gBo[8]; uint32_t sBo[8];
#pragma unroll
    for (int i = 0; i < 8; i++) {
        int f = tid + i * 256, n = f >> 3, c4 = (f & 7) * 4;
        gBo[i] = n * CIN + c4;
        sBo[i] = (uint32_t)(STG_A + n * BST + c4) * 4;
    }

#define ISSUE(t, b) do {                                                 \
        uint32_t base = smb + (uint32_t)(b) * (STAGE * 4);               \
        _Pragma("unroll")                                                \
        for (int i = 0; i < 4; i++) cpa16(base + sAo[i], Ag + gAo[i] + 32*(t)); \
        _Pragma("unroll")                                                \
        for (int i = 0; i < 8; i++) cpa16(base + sBo[i], Bg + gBo[i] + 32*(t)); \
        CP_COMMIT();                                                     \
    } while (0)

    float c[4][8][4];
#pragma unroll
    for (int mt = 0; mt < 4; mt++)
#pragma unroll
        for (int nt = 0; nt < 8; nt++)
#pragma unroll
            for (int l = 0; l < 4; l++) c[mt][nt][l] = 0.f;

    ISSUE(0, 0);
    ISSUE(1, 1);

#pragma unroll
    for (int t = 0; t < 8; t++) {
        if (t < 7) CP_WAIT1(); else CP_WAIT0();
        __syncthreads();
        if (t < 6) ISSUE(t + 2, (t + 2) % NSTAGE);

        const float* As = sm + (t % NSTAGE) * STAGE;
        const float* Bs = As + STG_A;
#pragma unroll
        for (int ks = 0; ks < 4; ks++) {
            const int k8 = ks * 8 + (lane & 3);
            uint32_t a[4][4];
#pragma unroll
            for (int mt = 0; mt < 4; mt++) {
                const float* ap = As + (wm * 64 + mt * 16 + (lane >> 2)) * AST;
                a[mt][0] = __float_as_uint(ap[k8]);
                a[mt][1] = __float_as_uint(ap[8 * AST + k8]);
                a[mt][2] = __float_as_uint(ap[k8 + 4]);
                a[mt][3] = __float_as_uint(ap[8 * AST + k8 + 4]);
            }
#pragma unroll
            for (int nt = 0; nt < 8; nt++) {
                const float* bp = Bs + (wn * 64 + nt * 8 + (lane >> 2)) * BST;
                uint32_t b0 = __float_as_uint(bp[k8]);
                uint32_t b1 = __float_as_uint(bp[k8 + 4]);
#pragma unroll
                for (int mt = 0; mt < 4; mt++) mma8(c[mt][nt], a[mt], b0, b1);
            }
        }
        __syncthreads();
    }

    // ---- epilogue: raw write + per-channel stats ----
    const int kof = 2 * bxp + (wn >> 1);
    float* ow = out + ((size_t)kof * NR + m0) * COUT + (wn & 1) * 64;
#pragma unroll
    for (int mt = 0; mt < 4; mt++) {
        int r = wm * 64 + mt * 16 + (lane >> 2);
#pragma unroll
        for (int nt = 0; nt < 8; nt++) {
            int dc = nt * 8 + 2 * (lane & 3);
            *(float2*)&ow[(size_t)r * COUT + dc] =
                make_float2(c[mt][nt][0], c[mt][nt][1]);
            *(float2*)&ow[(size_t)(r + 8) * COUT + dc] =
                make_float2(c[mt][nt][2], c[mt][nt][3]);
        }
    }

#pragma unroll
    for (int nt = 0; nt < 8; nt++) {
        float s0 = 0.f, s1 = 0.f, q0 = 0.f, q1 = 0.f;
#pragma unroll
        for (int mt = 0; mt < 4; mt++) {
            float v0 = c[mt][nt][0], v1 = c[mt][nt][1];
            float v2 = c[mt][nt][2], v3 = c[mt][nt][3];
            s0 += v0 + v2;           s1 += v1 + v3;
            q0 += v0 * v0 + v2 * v2; q1 += v1 * v1 + v3 * v3;
        }
#pragma unroll
        for (int off = 4; off < 32; off <<= 1) {
            s0 += __shfl_xor_sync(0xffffffffu, s0, off);
            s1 += __shfl_xor_sync(0xffffffffu, s1, off);
            q0 += __shfl_xor_sync(0xffffffffu, q0, off);
            q1 += __shfl_xor_sync(0xffffffffu, q1, off);
        }
        if (lane < 4) {
            int col = (wn & 1) * 64 + nt * 8 + 2 * lane;
            atomicAdd(&ssum[col],     s0); atomicAdd(&ssum[col + 1], s1);
            atomicAdd(&ssq[col],      q0); atomicAdd(&ssq[col + 1],  q1);
        }
    }
    __syncthreads();
    if (tid < COUT) {
        atomicAdd(&g_sum[tid],   ssum[tid]);
        atomicAdd(&g_sumsq[tid], ssq[tid]);
    }
}

__global__ void k_stats(const float* __restrict__ gamma, const float* __restrict__ beta) {
    int t = threadIdx.x;
    if (t < COUT) {
        float mean = g_sum[t] / CNTF;
        float var  = g_sumsq[t] / CNTF - mean * mean;
        float A = gamma[t] * rsqrtf(var + 1e-5f);
        g_sa[t] = A;
        g_sb[t] = beta[t] - mean * A;
    }
}

__global__ __launch_bounds__(256) void k_bnrelu(float* __restrict__ o) {
    int i = blockIdx.x * 256 + threadIdx.x;
    float4* o4 = (float4*)o;
    const float4* a4 = (const float4*)g_sa;
    const float4* b4 = (const float4*)g_sb;
    float4 v = o4[i];
    float4 a = a4[i & 31], b = b4[i & 31];
    v.x = fmaxf(fmaf(v.x, a.x, b.x), 0.f);
    v.y = fmaxf(fmaf(v.y, a.y, b.y), 0.f);
    v.z = fmaxf(fmaf(v.z, a.z, b.z), 0.f);
    v.w = fmaxf(fmaf(v.w, a.w, b.w), 0.f);
    o4[i] = v;
}

extern "C" void kernel_launch(void* const* d_in, const int* in_sizes, int n_in,
                              void* d_out, int out_size) {
    const float* X     = (const float*)d_in[0];   // [65536, 256]
    const float* W     = (const float*)d_in[1];   // [8, 256, 128]
    const float* gamma = (const float*)d_in[2];   // [128]
    const float* beta  = (const float*)d_in[3];   // [128]
    float* out = (float*)d_out;                   // [8*65536, 128]

    cudaFuncSetAttribute(k_gemm, cudaFuncAttributeMaxDynamicSharedMemorySize, SMEM_BYTES);
    k_zero<<<1, 128>>>();
    k_wt<<<1024, 256>>>(W);
    k_gemm<<<dim3(4, NR / BM), 256, SMEM_BYTES>>>(X, out);
    k_stats<<<1, 128>>>(gamma, beta);
    k_bnrelu<<<(KOFF * NR * COUT) / 4 / 256, 256>>>(out);
}

// round 6
// speedup vs baseline: 1.4441x; 1.0053x over previous
#include <cuda_runtime.h>
#include <cstdint>

#define NR 65536
#define CIN 256
#define COUT 128
#define KOFF 8
#define CNTF 524288.0f

#define BM 128
#define BN 256            // spans 2 k-offsets
#define BK 32
#define AST 36
#define BST 36
#define STG_A (BM * AST)          // 4608 floats
#define STG_B (BN * BST)          // 9216 floats
#define STAGE (STG_A + STG_B)     // 13824 floats
#define NSTAGE 3
#define SMEM_BYTES ((NSTAGE * STAGE + 256) * 4)

__device__ __align__(16) float g_Wt[KOFF * COUT * CIN];   // [n=k*128+d][c], tf32-rna
__device__ __align__(16) float g_sum[COUT];
__device__ __align__(16) float g_sumsq[COUT];
__device__ __align__(16) float g_sa[COUT];
__device__ __align__(16) float g_sb[COUT];

__device__ __forceinline__ float f2tf32(float x) {
    uint32_t u; asm("cvt.rna.tf32.f32 %0, %1;" : "=r"(u) : "f"(x));
    return __uint_as_float(u);
}
__device__ __forceinline__ uint32_t smem_u32(const void* p) {
    uint32_t a;
    asm("{ .reg .u64 t; cvta.to.shared.u64 t, %1; cvt.u32.u64 %0, t; }" : "=r"(a) : "l"(p));
    return a;
}
__device__ __forceinline__ void cpa16(uint32_t s, const float* g) {
    asm volatile("cp.async.cg.shared.global [%0], [%1], 16;" :: "r"(s), "l"(g));
}
#define CP_COMMIT() asm volatile("cp.async.commit_group;" ::: "memory")
#define CP_WAIT1()  asm volatile("cp.async.wait_group 1;" ::: "memory")
#define CP_WAIT0()  asm volatile("cp.async.wait_group 0;" ::: "memory")

__device__ __forceinline__ void mma8(float* c, const uint32_t* a, uint32_t b0, uint32_t b1) {
    asm volatile(
        "mma.sync.aligned.m16n8k8.row.col.f32.tf32.tf32.f32 "
        "{%0,%1,%2,%3}, {%4,%5,%6,%7}, {%8,%9}, {%0,%1,%2,%3};"
        : "+f"(c[0]), "+f"(c[1]), "+f"(c[2]), "+f"(c[3])
        : "r"(a[0]), "r"(a[1]), "r"(a[2]), "r"(a[3]), "r"(b0), "r"(b1));
}

__global__ void k_zero() {
    int t = threadIdx.x;
    if (t < COUT) { g_sum[t] = 0.f; g_sumsq[t] = 0.f; }
}

// g_Wt[n][c] = rna_tf32(W[k][c][d]), n = k*128 + d; half = 0/1
__global__ void k_wt(const float* __restrict__ W, int half) {
    int idx = half * 131072 + blockIdx.x * 256 + threadIdx.x;
    int n = idx >> 8, c = idx & 255;
    int k = n >> 7, d = n & 127;
    g_Wt[idx] = f2tf32(W[(k << 15) + (c << 7) + d]);
}

__global__ __launch_bounds__(256, 1)
void k_gemm(const float* __restrict__ X, float* __restrict__ out) {
    extern __shared__ float sm[];
    float* ssum = sm + NSTAGE * STAGE;
    float* ssq  = ssum + COUT;

    const int tid = threadIdx.x, lane = tid & 31, wid = tid >> 5;
    const int wm = wid >> 2, wn = wid & 3;       // 2x4 warps, 64x64 tiles
    const int bxp = blockIdx.x;                  // 0..3 (pair of k-offsets)
    const int m0 = blockIdx.y * BM;

    if (tid < COUT) { ssum[tid] = 0.f; ssq[tid] = 0.f; }

    const float* Ag = X + (size_t)m0 * CIN;
    const float* Bg = g_Wt + (size_t)(bxp * BN) * CIN;
    const uint32_t smb = smem_u32(sm);

    int gAo[4]; uint32_t sAo[4];
#pragma unroll
    for (int i = 0; i < 4; i++) {
        int f = tid + i * 256, r = f >> 3, c4 = (f & 7) * 4;
        gAo[i] = r * CIN + c4;
        sAo[i] = (uint32_t)(r * AST + c4) * 4;
    }
    int gBo[8]; uint32_t sBo[8];
#pragma unroll
    for (int i = 0; i < 8; i++) {
        int f = tid + i * 256, n = f >> 3, c4 = (f & 7) * 4;
        gBo[i] = n * CIN + c4;
        sBo[i] = (uint32_t)(STG_A + n * BST + c4) * 4;
    }

#define ISSUE(t, b) do {                                                        \
        uint32_t base = smb + (uint32_t)(b) * (STAGE * 4);                      \
        _Pragma("unroll")                                                       \
        for (int i = 0; i < 4; i++) cpa16(base + sAo[i], Ag + gAo[i] + 32*(t)); \
        _Pragma("unroll")                                                       \
        for (int i = 0; i < 8; i++) cpa16(base + sBo[i], Bg + gBo[i] + 32*(t)); \
        CP_COMMIT();                                                            \
    } while (0)

    float c[4][8][4];
#pragma unroll
    for (int mt = 0; mt < 4; mt++)
#pragma unroll
        for (int nt = 0; nt < 8; nt++)
#pragma unroll
            for (int l = 0; l < 4; l++) c[mt][nt][l] = 0.f;

    uint32_t afr[2][4][4], bfr[2][8][2];

#define LDFRAG(buf, As, Bs, ks) do {                                            \
        const int k8 = (ks) * 8 + (lane & 3);                                   \
        _Pragma("unroll")                                                       \
        for (int mt = 0; mt < 4; mt++) {                                        \
            const float* ap = (As) + (wm * 64 + mt * 16 + (lane >> 2)) * AST;   \
            afr[buf][mt][0] = __float_as_uint(ap[k8]);                          \
            afr[buf][mt][1] = __float_as_uint(ap[8 * AST + k8]);                \
            afr[buf][mt][2] = __float_as_uint(ap[k8 + 4]);                      \
            afr[buf][mt][3] = __float_as_uint(ap[8 * AST + k8 + 4]);            \
        }                                                                       \
        _Pragma("unroll")                                                       \
        for (int nt = 0; nt < 8; nt++) {                                        \
            const float* bp = (Bs) + (wn * 64 + nt * 8 + (lane >> 2)) * BST;    \
            bfr[buf][nt][0] = __float_as_uint(bp[k8]);                          \
            bfr[buf][nt][1] = __float_as_uint(bp[k8 + 4]);                      \
        } } while (0)

    ISSUE(0, 0);
    ISSUE(1, 1);

#pragma unroll
    for (int t = 0; t < 8; t++) {
        if (t < 7) CP_WAIT1(); else CP_WAIT0();
        __syncthreads();
        if (t < 6) ISSUE(t + 2, (t + 2) % NSTAGE);

        const float* As = sm + (t % NSTAGE) * STAGE;
        const float* Bs = As + STG_A;

        LDFRAG(0, As, Bs, 0);
#pragma unroll
        for (int ks = 0; ks < 4; ks++) {
            const int cur = ks & 1;
            if (ks < 3) LDFRAG(cur ^ 1, As, Bs, ks + 1);
#pragma unroll
            for (int nt = 0; nt < 8; nt++) {
#pragma unroll
                for (int mt = 0; mt < 4; mt++)
                    mma8(c[mt][nt], afr[cur][mt], bfr[cur][nt][0], bfr[cur][nt][1]);
            }
        }
    }

    // ---- epilogue: raw write + per-channel stats ----
    const int kof = 2 * bxp + (wn >> 1);
    float* ow = out + ((size_t)kof * NR + m0) * COUT + (wn & 1) * 64;
#pragma unroll
    for (int mt = 0; mt < 4; mt++) {
        int r = wm * 64 + mt * 16 + (lane >> 2);
#pragma unroll
        for (int nt = 0; nt < 8; nt++) {
            int dc = nt * 8 + 2 * (lane & 3);
            *(float2*)&ow[(size_t)r * COUT + dc] =
                make_float2(c[mt][nt][0], c[mt][nt][1]);
            *(float2*)&ow[(size_t)(r + 8) * COUT + dc] =
                make_float2(c[mt][nt][2], c[mt][nt][3]);
        }
    }

#pragma unroll
    for (int nt = 0; nt < 8; nt++) {
        float s0 = 0.f, s1 = 0.f, q0 = 0.f, q1 = 0.f;
#pragma unroll
        for (int mt = 0; mt < 4; mt++) {
            float v0 = c[mt][nt][0], v1 = c[mt][nt][1];
            float v2 = c[mt][nt][2], v3 = c[mt][nt][3];
            s0 += v0 + v2;           s1 += v1 + v3;
            q0 += v0 * v0 + v2 * v2; q1 += v1 * v1 + v3 * v3;
        }
#pragma unroll
        for (int off = 4; off < 32; off <<= 1) {
            s0 += __shfl_xor_sync(0xffffffffu, s0, off);
            s1 += __shfl_xor_sync(0xffffffffu, s1, off);
            q0 += __shfl_xor_sync(0xffffffffu, q0, off);
            q1 += __shfl_xor_sync(0xffffffffu, q1, off);
        }
        if (lane < 4) {
            int col = (wn & 1) * 64 + nt * 8 + 2 * lane;
            atomicAdd(&ssum[col],     s0); atomicAdd(&ssum[col + 1], s1);
            atomicAdd(&ssq[col],      q0); atomicAdd(&ssq[col + 1],  q1);
        }
    }
    __syncthreads();
    if (tid < COUT) {
        atomicAdd(&g_sum[tid],   ssum[tid]);
        atomicAdd(&g_sumsq[tid], ssq[tid]);
    }
}

__global__ void k_stats(const float* __restrict__ gamma, const float* __restrict__ beta) {
    int t = threadIdx.x;
    if (t < COUT) {
        float mean = g_sum[t] / CNTF;
        float var  = g_sumsq[t] / CNTF - mean * mean;
        float A = gamma[t] * rsqrtf(var + 1e-5f);
        g_sa[t] = A;
        g_sb[t] = beta[t] - mean * A;
    }
}

__global__ __launch_bounds__(256) void k_bnrelu(float* __restrict__ o) {
    int i = blockIdx.x * 256 + threadIdx.x;
    float4* o4 = (float4*)o;
    const float4* a4 = (const float4*)g_sa;
    const float4* b4 = (const float4*)g_sb;
    float4 v = o4[i];
    float4 a = a4[i & 31], b = b4[i & 31];
    v.x = fmaxf(fmaf(v.x, a.x, b.x), 0.f);
    v.y = fmaxf(fmaf(v.y, a.y, b.y), 0.f);
    v.z = fmaxf(fmaf(v.z, a.z, b.z), 0.f);
    v.w = fmaxf(fmaf(v.w, a.w, b.w), 0.f);
    o4[i] = v;
}

extern "C" void kernel_launch(void* const* d_in, const int* in_sizes, int n_in,
                              void* d_out, int out_size) {
    const float* X     = (const float*)d_in[0];   // [65536, 256]
    const float* W     = (const float*)d_in[1];   // [8, 256, 128]
    const float* gamma = (const float*)d_in[2];   // [128]
    const float* beta  = (const float*)d_in[3];   // [128]
    float* out = (float*)d_out;                   // [8*65536, 128]

    cudaFuncSetAttribute(k_gemm, cudaFuncAttributeMaxDynamicSharedMemorySize, SMEM_BYTES);
    k_zero<<<1, 128>>>();                          // launch 1
    k_wt<<<512, 256>>>(W, 0);                      // launch 2
    k_wt<<<512, 256>>>(W, 1);                      // launch 3
    k_gemm<<<dim3(4, NR / BM), 256, SMEM_BYTES>>>(X, out);   // launch 4 -> profiled
    k_stats<<<1, 128>>>(gamma, beta);
    k_bnrelu<<<(KOFF * NR * COUT) / 4 / 256, 256>>>(out);
}

// round 7
// speedup vs baseline: 1.5011x; 1.0395x over previous
#include <cuda_runtime.h>
#include <cstdint>

#define NR 65536
#define CIN 256
#define COUT 128
#define KOFF 8
#define CNTF 524288.0f

#define BM 128
#define BN 128
#define BK 32
#define AST 36
#define STG_A (BM * AST)          // 4608 floats
#define STAGE (2 * STG_A)         // 9216 floats (A + B)
#define NSTAGE 3
#define SMEM_BYTES ((NSTAGE * STAGE + 256) * 4)   // 111616 B

__device__ __align__(16) float g_Wt[KOFF * COUT * CIN];   // [n=k*128+d][c], tf32-rna
__device__ __align__(16) float g_sum[COUT];
__device__ __align__(16) float g_sumsq[COUT];
__device__ __align__(16) float g_sa[COUT];
__device__ __align__(16) float g_sb[COUT];

__device__ __forceinline__ float f2tf32(float x) {
    uint32_t u; asm("cvt.rna.tf32.f32 %0, %1;" : "=r"(u) : "f"(x));
    return __uint_as_float(u);
}
__device__ __forceinline__ uint32_t smem_u32(const void* p) {
    uint32_t a;
    asm("{ .reg .u64 t; cvta.to.shared.u64 t, %1; cvt.u32.u64 %0, t; }" : "=r"(a) : "l"(p));
    return a;
}
__device__ __forceinline__ void cpa16(uint32_t s, const float* g) {
    asm volatile("cp.async.cg.shared.global [%0], [%1], 16;" :: "r"(s), "l"(g));
}
#define CP_COMMIT() asm volatile("cp.async.commit_group;" ::: "memory")
#define CP_WAIT1()  asm volatile("cp.async.wait_group 1;" ::: "memory")
#define CP_WAIT0()  asm volatile("cp.async.wait_group 0;" ::: "memory")

__device__ __forceinline__ void mma8(float* c, const uint32_t* a, uint32_t b0, uint32_t b1) {
    asm volatile(
        "mma.sync.aligned.m16n8k8.row.col.f32.tf32.tf32.f32 "
        "{%0,%1,%2,%3}, {%4,%5,%6,%7}, {%8,%9}, {%0,%1,%2,%3};"
        : "+f"(c[0]), "+f"(c[1]), "+f"(c[2]), "+f"(c[3])
        : "r"(a[0]), "r"(a[1]), "r"(a[2]), "r"(a[3]), "r"(b0), "r"(b1));
}

__global__ void k_zero() {
    int t = threadIdx.x;
    if (t < COUT) { g_sum[t] = 0.f; g_sumsq[t] = 0.f; }
}

// g_Wt[n][c] = rna_tf32(W[k][c][d]), n = k*128 + d; half = 0/1
__global__ void k_wt(const float* __restrict__ W, int half) {
    int idx = half * 131072 + blockIdx.x * 256 + threadIdx.x;
    int n = idx >> 8, c = idx & 255;
    int k = n >> 7, d = n & 127;
    g_Wt[idx] = f2tf32(W[(k << 15) + (c << 7) + d]);
}

__global__ __launch_bounds__(256, 2)
void k_gemm(const float* __restrict__ X, float* __restrict__ out) {
    extern __shared__ float sm[];
    float* ssum = sm + NSTAGE * STAGE;
    float* ssq  = ssum + COUT;

    const int tid = threadIdx.x, lane = tid & 31, wid = tid >> 5;
    const int wm = wid >> 1, wn = wid & 1;       // 4x2 warps, 32x64 tiles
    const int bx = blockIdx.x;                   // k offset 0..7
    const int m0 = blockIdx.y * BM;

    if (tid < COUT) { ssum[tid] = 0.f; ssq[tid] = 0.f; }

    const float* Ag = X + (size_t)m0 * CIN;
    const float* Bg = g_Wt + (size_t)(bx * BN) * CIN;
    const uint32_t smb = smem_u32(sm);

    int gO[4]; uint32_t sAo[4];
#pragma unroll
    for (int i = 0; i < 4; i++) {
        int f = tid + i * 256, r = f >> 3, c4 = (f & 7) * 4;
        gO[i]  = r * CIN + c4;                       // same pattern for A and B
        sAo[i] = (uint32_t)(r * AST + c4) * 4;
    }

#define ISSUE(t, b) do {                                                        \
        uint32_t base = smb + (uint32_t)(b) * (STAGE * 4);                      \
        _Pragma("unroll")                                                       \
        for (int i = 0; i < 4; i++) {                                           \
            cpa16(base + sAo[i],               Ag + gO[i] + 32 * (t));          \
            cpa16(base + sAo[i] + STG_A * 4,   Bg + gO[i] + 32 * (t));          \
        }                                                                       \
        CP_COMMIT();                                                            \
    } while (0)

    float c[2][8][4];
#pragma unroll
    for (int mt = 0; mt < 2; mt++)
#pragma unroll
        for (int nt = 0; nt < 8; nt++)
#pragma unroll
            for (int l = 0; l < 4; l++) c[mt][nt][l] = 0.f;

    ISSUE(0, 0);
    ISSUE(1, 1);

#pragma unroll
    for (int t = 0; t < 8; t++) {
        if (t < 7) CP_WAIT1(); else CP_WAIT0();
        __syncthreads();
        if (t < 6) ISSUE(t + 2, (t + 2) % NSTAGE);

        const float* As = sm + (t % NSTAGE) * STAGE;
        const float* Bs = As + STG_A;
#pragma unroll
        for (int ks = 0; ks < 4; ks++) {
            const int k8 = ks * 8 + (lane & 3);
            uint32_t a[2][4];
#pragma unroll
            for (int mt = 0; mt < 2; mt++) {
                const float* ap = As + (wm * 32 + mt * 16 + (lane >> 2)) * AST;
                a[mt][0] = __float_as_uint(ap[k8]);
                a[mt][1] = __float_as_uint(ap[8 * AST + k8]);
                a[mt][2] = __float_as_uint(ap[k8 + 4]);
                a[mt][3] = __float_as_uint(ap[8 * AST + k8 + 4]);
            }
#pragma unroll
            for (int nt = 0; nt < 8; nt++) {
                const float* bp = Bs + (wn * 64 + nt * 8 + (lane >> 2)) * AST;
                uint32_t b0 = __float_as_uint(bp[k8]);
                uint32_t b1 = __float_as_uint(bp[k8 + 4]);
                mma8(c[0][nt], a[0], b0, b1);
                mma8(c[1][nt], a[1], b0, b1);
            }
        }
        __syncthreads();
    }

    // ---- epilogue: raw write + per-channel stats ----
    float* ow = out + ((size_t)bx * NR + m0) * COUT;
#pragma unroll
    for (int mt = 0; mt < 2; mt++) {
        int r = wm * 32 + mt * 16 + (lane >> 2);
#pragma unroll
        for (int nt = 0; nt < 8; nt++) {
            int dc = wn * 64 + nt * 8 + 2 * (lane & 3);
            *(float2*)&ow[(size_t)r * COUT + dc] =
                make_float2(c[mt][nt][0], c[mt][nt][1]);
            *(float2*)&ow[(size_t)(r + 8) * COUT + dc] =
                make_float2(c[mt][nt][2], c[mt][nt][3]);
        }
    }

#pragma unroll
    for (int nt = 0; nt < 8; nt++) {
        float s0 = 0.f, s1 = 0.f, q0 = 0.f, q1 = 0.f;
#pragma unroll
        for (int mt = 0; mt < 2; mt++) {
            float v0 = c[mt][nt][0], v1 = c[mt][nt][1];
            float v2 = c[mt][nt][2], v3 = c[mt][nt][3];
            s0 += v0 + v2;           s1 += v1 + v3;
            q0 += v0 * v0 + v2 * v2; q1 += v1 * v1 + v3 * v3;
        }
#pragma unroll
        for (int off = 4; off < 32; off <<= 1) {
            s0 += __shfl_xor_sync(0xffffffffu, s0, off);
            s1 += __shfl_xor_sync(0xffffffffu, s1, off);
            q0 += __shfl_xor_sync(0xffffffffu, q0, off);
            q1 += __shfl_xor_sync(0xffffffffu, q1, off);
        }
        if (lane < 4) {
            int col = wn * 64 + nt * 8 + 2 * lane;
            atomicAdd(&ssum[col],     s0); atomicAdd(&ssum[col + 1], s1);
            atomicAdd(&ssq[col],      q0); atomicAdd(&ssq[col + 1],  q1);
        }
    }
    __syncthreads();
    if (tid < COUT) {
        atomicAdd(&g_sum[tid],   ssum[tid]);
        atomicAdd(&g_sumsq[tid], ssq[tid]);
    }
}

__global__ void k_stats(const float* __restrict__ gamma, const float* __restrict__ beta) {
    int t = threadIdx.x;
    if (t < COUT) {
        float mean = g_sum[t] / CNTF;
        float var  = g_sumsq[t] / CNTF - mean * mean;
        float A = gamma[t] * rsqrtf(var + 1e-5f);
        g_sa[t] = A;
        g_sb[t] = beta[t] - mean * A;
    }
}

__global__ __launch_bounds__(256) void k_bnrelu(float* __restrict__ o) {
    int i = blockIdx.x * 256 + threadIdx.x;
    float4* o4 = (float4*)o;
    const float4* a4 = (const float4*)g_sa;
    const float4* b4 = (const float4*)g_sb;
    float4 v = o4[i];
    float4 a = a4[i & 31], b = b4[i & 31];
    v.x = fmaxf(fmaf(v.x, a.x, b.x), 0.f);
    v.y = fmaxf(fmaf(v.y, a.y, b.y), 0.f);
    v.z = fmaxf(fmaf(v.z, a.z, b.z), 0.f);
    v.w = fmaxf(fmaf(v.w, a.w, b.w), 0.f);
    o4[i] = v;
}

extern "C" void kernel_launch(void* const* d_in, const int* in_sizes, int n_in,
                              void* d_out, int out_size) {
    const float* X     = (const float*)d_in[0];   // [65536, 256]
    const float* W     = (const float*)d_in[1];   // [8, 256, 128]
    const float* gamma = (const float*)d_in[2];   // [128]
    const float* beta  = (const float*)d_in[3];   // [128]
    float* out = (float*)d_out;                   // [8*65536, 128]

    cudaFuncSetAttribute(k_gemm, cudaFuncAttributeMaxDynamicSharedMemorySize, SMEM_BYTES);
    k_zero<<<1, 128>>>();                                     // launch 1
    k_wt<<<512, 256>>>(W, 0);                                 // launch 2
    k_wt<<<512, 256>>>(W, 1);                                 // launch 3
    k_gemm<<<dim3(KOFF, NR / BM), 256, SMEM_BYTES>>>(X, out); // launch 4 -> profiled
    k_stats<<<1, 128>>>(gamma, beta);
    k_bnrelu<<<(KOFF * NR * COUT) / 4 / 256, 256>>>(out);
}